// round 5
// baseline (speedup 1.0000x reference)
#include <cuda_runtime.h>
#include <math.h>

#define S_LEN 2048
#define HID   4096
#define NH    32
#define NKV   8
#define HD    128
#define TOPK  16

// ---------------- scratch (device globals: no allocations allowed) ----------
__device__ float g_Q[(size_t)S_LEN * HID];        // 32 MB
__device__ float g_K[(size_t)S_LEN * NKV * HD];   // 8 MB
__device__ float g_V[(size_t)S_LEN * NKV * HD];   // 8 MB
__device__ float g_attn[(size_t)S_LEN * HID];     // 32 MB
__device__ float g_cos[S_LEN * 64];
__device__ float g_sin[S_LEN * 64];

// ---------------- RoPE table ------------------------------------------------
// Emulate the host / correctly-rounded (glibc or HloEvaluator) fp32 pipeline:
//   expo = (2i)/128                         (exact f32)
//   p    = f32( pow_f64(500000, expo) )     (== CR powf)
//   inv  = 1.0f / p                         (f32 divide, rn)
//   ang  = f32( pos * inv )                 (f32 multiply, rn)
//   cos  = f32( cos_f64(ang) ), sin = f32( sin_f64(ang) )   (== CR cosf/sinf)
__global__ void rope_table_kernel() {
    int idx = blockIdx.x * blockDim.x + threadIdx.x;
    if (idx >= S_LEN * 64) return;
    int s = idx >> 6;
    int i = idx & 63;
    double expo = (double)(2 * i) / 128.0;            // exact
    float  p    = (float)pow(500000.0, expo);         // CR powf emulation
    float  inv  = __fdiv_rn(1.0f, p);
    float  ang  = __fmul_rn((float)s, inv);
    g_cos[idx] = (float)cos((double)ang);             // CR cosf emulation
    g_sin[idx] = (float)sin((double)ang);             // CR sinf emulation
}

// ---------------- RoPE apply (in place, explicit rn mul/add, no FMA) --------
__global__ void rope_apply_kernel(float* __restrict__ X, int nheads) {
    int idx = blockIdx.x * blockDim.x + threadIdx.x;
    int total = S_LEN * nheads * 64;
    if (idx >= total) return;
    int i = idx & 63;
    int h = (idx >> 6) % nheads;
    int s = idx / (nheads * 64);
    size_t base = ((size_t)s * nheads + h) * HD + i;
    float c  = g_cos[(s << 6) + i];
    float sn = g_sin[(s << 6) + i];
    float x1 = X[base];
    float x2 = X[base + 64];
    float t1 = __fmul_rn(x1, c);
    float t2 = __fmul_rn(x2, sn);
    float u1 = __fmul_rn(x2, c);
    float u2 = __fmul_rn(x1, sn);
    X[base]      = __fadd_rn(t1, -t2);
    X[base + 64] = __fadd_rn(u1, u2);
}

// ---------------- SGEMM: C[M,N] = A[M,K] @ B[N,K]^T ------------------------
// BM=BN=128, BK=16, 256 threads, 8x8 per thread. KAHAN: compensated acc.
template <bool KAHAN>
__global__ __launch_bounds__(256) void sgemm_nt(
    const float* __restrict__ A, const float* __restrict__ B,
    float* __restrict__ C, int M, int N, int K)
{
    __shared__ float As[16 * 132];  // [k][m], padded
    __shared__ float Bs[16 * 132];  // [k][n], padded

    const int tid = threadIdx.x;
    const int bm = blockIdx.y * 128;
    const int bn = blockIdx.x * 128;
    const int lr = tid >> 2;            // 0..63
    const int lc = (tid & 3) << 2;      // 0,4,8,12
    const int ty = tid >> 4;            // 0..15
    const int tx = tid & 15;            // 0..15

    float acc[8][8];
    float cmp[8][8];
#pragma unroll
    for (int i = 0; i < 8; i++)
#pragma unroll
        for (int j = 0; j < 8; j++) { acc[i][j] = 0.0f; cmp[i][j] = 0.0f; }

    const float* Ap = A + (size_t)(bm + lr) * K + lc;
    const float* Bp = B + (size_t)(bn + lr) * K + lc;

    for (int k0 = 0; k0 < K; k0 += 16) {
        float4 a0 = *(const float4*)(Ap + k0);
        float4 a1 = *(const float4*)(Ap + (size_t)64 * K + k0);
        float4 b0 = *(const float4*)(Bp + k0);
        float4 b1 = *(const float4*)(Bp + (size_t)64 * K + k0);
        __syncthreads();
        As[(lc + 0) * 132 + lr] = a0.x;
        As[(lc + 1) * 132 + lr] = a0.y;
        As[(lc + 2) * 132 + lr] = a0.z;
        As[(lc + 3) * 132 + lr] = a0.w;
        As[(lc + 0) * 132 + lr + 64] = a1.x;
        As[(lc + 1) * 132 + lr + 64] = a1.y;
        As[(lc + 2) * 132 + lr + 64] = a1.z;
        As[(lc + 3) * 132 + lr + 64] = a1.w;
        Bs[(lc + 0) * 132 + lr] = b0.x;
        Bs[(lc + 1) * 132 + lr] = b0.y;
        Bs[(lc + 2) * 132 + lr] = b0.z;
        Bs[(lc + 3) * 132 + lr] = b0.w;
        Bs[(lc + 0) * 132 + lr + 64] = b1.x;
        Bs[(lc + 1) * 132 + lr + 64] = b1.y;
        Bs[(lc + 2) * 132 + lr + 64] = b1.z;
        Bs[(lc + 3) * 132 + lr + 64] = b1.w;
        __syncthreads();

#pragma unroll
        for (int kk = 0; kk < 16; kk++) {
            float ar[8], br[8];
            *(float4*)(ar)     = *(float4*)&As[kk * 132 + ty * 8];
            *(float4*)(ar + 4) = *(float4*)&As[kk * 132 + ty * 8 + 4];
            *(float4*)(br)     = *(float4*)&Bs[kk * 132 + tx * 8];
            *(float4*)(br + 4) = *(float4*)&Bs[kk * 132 + tx * 8 + 4];
#pragma unroll
            for (int i = 0; i < 8; i++)
#pragma unroll
                for (int j = 0; j < 8; j++) {
                    if (KAHAN) {
                        float y = fmaf(ar[i], br[j], -cmp[i][j]);
                        float t = __fadd_rn(acc[i][j], y);
                        cmp[i][j] = __fadd_rn(__fadd_rn(t, -acc[i][j]), -y);
                        acc[i][j] = t;
                    } else {
                        acc[i][j] = fmaf(ar[i], br[j], acc[i][j]);
                    }
                }
        }
    }

#pragma unroll
    for (int i = 0; i < 8; i++) {
        size_t row = (size_t)(bm + ty * 8 + i) * N + bn + tx * 8;
#pragma unroll
        for (int j = 0; j < 8; j++)
            if (KAHAN) acc[i][j] = __fadd_rn(acc[i][j], -cmp[i][j]);
        float4 v0 = make_float4(acc[i][0], acc[i][1], acc[i][2], acc[i][3]);
        float4 v1 = make_float4(acc[i][4], acc[i][5], acc[i][6], acc[i][7]);
        *(float4*)&C[row]     = v0;
        *(float4*)&C[row + 4] = v1;
    }
}

// ---------------- fused top-k attention (Kahan score dot) -------------------
__global__ __launch_bounds__(256) void attn_kernel(
    const float* __restrict__ Q, const float* __restrict__ Kd,
    const float* __restrict__ V, float* __restrict__ O)
{
    extern __shared__ float sm[];
    float* Qs = sm;                      // [64][129]
    float* Ks = Qs + 64 * 129;           // [64][129]
    float* Ss = Ks + 64 * 129;           // [64][64]
    float* Tv = Ss + 64 * 64;            // [64][16] values -> weights
    int*   Ti = (int*)(Tv + 64 * TOPK);  // [64][16]

    const int tid = threadIdx.x;
    const int h   = blockIdx.y;
    const int kvh = h >> 2;
    const int q0  = blockIdx.x * 64;
    const float sqrtd = 11.313708498984761f;  // f32(sqrt(128))

    // load Q tile (64 x 128)
#pragma unroll
    for (int it = 0; it < 8; it++) {
        int idx = tid + it * 256;
        int r = idx >> 5;
        int d4 = (idx & 31) << 2;
        float4 v = *(const float4*)&Q[((size_t)(q0 + r) * NH + h) * HD + d4];
        Qs[r * 129 + d4 + 0] = v.x;
        Qs[r * 129 + d4 + 1] = v.y;
        Qs[r * 129 + d4 + 2] = v.z;
        Qs[r * 129 + d4 + 3] = v.w;
    }
    if (tid < 64) {
#pragma unroll
        for (int j = 0; j < TOPK; j++) Tv[tid * TOPK + j] = -INFINITY;
    }
    float vmin = -INFINITY;
    int minpos = 0;

    const int ty = tid >> 4, tx = tid & 15;
    const int r0 = ty << 2, c0 = tx << 2;

    for (int kt = 0; kt < S_LEN / 64; kt++) {
        __syncthreads();
        // load K tile (64 x 128) for this kv head
#pragma unroll
        for (int it = 0; it < 8; it++) {
            int idx = tid + it * 256;
            int r = idx >> 5;
            int d4 = (idx & 31) << 2;
            float4 v = *(const float4*)&Kd[((size_t)(kt * 64 + r) * NKV + kvh) * HD + d4];
            Ks[r * 129 + d4 + 0] = v.x;
            Ks[r * 129 + d4 + 1] = v.y;
            Ks[r * 129 + d4 + 2] = v.z;
            Ks[r * 129 + d4 + 3] = v.w;
        }
        __syncthreads();

        // 4x4 micro-tile score compute with Kahan accumulation
        float acc[4][4], cmp[4][4];
#pragma unroll
        for (int i = 0; i < 4; i++)
#pragma unroll
            for (int j = 0; j < 4; j++) { acc[i][j] = 0.0f; cmp[i][j] = 0.0f; }

        const float* qp = Qs + r0 * 129;
        const float* kp = Ks + c0 * 129;
#pragma unroll 2
        for (int d = 0; d < 128; d++) {
            float a[4], b[4];
            a[0] = qp[d]; a[1] = qp[129 + d]; a[2] = qp[258 + d]; a[3] = qp[387 + d];
            b[0] = kp[d]; b[1] = kp[129 + d]; b[2] = kp[258 + d]; b[3] = kp[387 + d];
#pragma unroll
            for (int i = 0; i < 4; i++)
#pragma unroll
                for (int j = 0; j < 4; j++) {
                    float y = fmaf(a[i], b[j], -cmp[i][j]);
                    float t = __fadd_rn(acc[i][j], y);
                    cmp[i][j] = __fadd_rn(__fadd_rn(t, -acc[i][j]), -y);
                    acc[i][j] = t;
                }
        }
#pragma unroll
        for (int i = 0; i < 4; i++)
#pragma unroll
            for (int j = 0; j < 4; j++) {
                float s = __fadd_rn(acc[i][j], -cmp[i][j]);
                Ss[(r0 + i) * 64 + c0 + j] = __fdiv_rn(s, sqrtd);
            }
        __syncthreads();

        // per-row top-16 maintenance (threads 0..63, one per q row)
        if (tid < 64) {
            int base = kt * 64;
            float* tvp = Tv + tid * TOPK;
            int*   tip = Ti + tid * TOPK;
            const float* srow = Ss + tid * 64;
            for (int c = 0; c < 64; c++) {
                float s = srow[c];
                if (s > vmin) {
                    tvp[minpos] = s;
                    tip[minpos] = base + c;
                    vmin = tvp[0]; minpos = 0;
#pragma unroll
                    for (int j = 1; j < TOPK; j++) {
                        float t = tvp[j];
                        if (t < vmin) { vmin = t; minpos = j; }
                    }
                }
            }
        }
    }
    __syncthreads();

    // softmax over top-16 per row
    if (tid < 64) {
        float* tvp = Tv + tid * TOPK;
        float m = -INFINITY;
#pragma unroll
        for (int j = 0; j < TOPK; j++) m = fmaxf(m, tvp[j]);
        float ssum = 0.0f;
#pragma unroll
        for (int j = 0; j < TOPK; j++) {
            float e = expf(tvp[j] - m);
            tvp[j] = e;
            ssum += e;
        }
        float inv = __fdiv_rn(1.0f, ssum);
#pragma unroll
        for (int j = 0; j < TOPK; j++) tvp[j] = __fmul_rn(tvp[j], inv);
    }
    __syncthreads();

    // weighted V gather: 64 rows x 128 dims
#pragma unroll
    for (int it = 0; it < 32; it++) {
        int idx = tid + it * 256;
        int r = idx >> 7;
        int d = idx & 127;
        const float* tvp = Tv + r * TOPK;
        const int*   tip = Ti + r * TOPK;
        float acc = 0.0f;
#pragma unroll
        for (int j = 0; j < TOPK; j++) {
            float w = tvp[j];
            int ki = tip[j];
            acc = fmaf(w, V[((size_t)ki * NKV + kvh) * HD + d], acc);
        }
        O[((size_t)(q0 + r) * NH + h) * HD + d] = acc;
    }
}

// ---------------- launch ----------------------------------------------------
extern "C" void kernel_launch(void* const* d_in, const int* in_sizes, int n_in,
                              void* d_out, int out_size)
{
    const float* hidden = (const float*)d_in[0];
    const float* Wq = (const float*)d_in[1];
    const float* Wk = (const float*)d_in[2];
    const float* Wv = (const float*)d_in[3];
    const float* Wo = (const float*)d_in[4];
    float* out = (float*)d_out;

    float *q, *k, *v, *at;
    cudaGetSymbolAddress((void**)&q,  g_Q);
    cudaGetSymbolAddress((void**)&k,  g_K);
    cudaGetSymbolAddress((void**)&v,  g_V);
    cudaGetSymbolAddress((void**)&at, g_attn);

    rope_table_kernel<<<(S_LEN * 64 + 255) / 256, 256>>>();

    dim3 gq(HID / 128, S_LEN / 128);        // (32,16)
    dim3 gkv(NKV * HD / 128, S_LEN / 128);  // (8,16)
    // Q, K projections: Kahan (feed the top-k comparison)
    sgemm_nt<true><<<gq,  256>>>(hidden, Wq, q, S_LEN, HID, HID);
    sgemm_nt<true><<<gkv, 256>>>(hidden, Wk, k, S_LEN, NKV * HD, HID);
    // V projection: plain fp32 (values only, no flips)
    sgemm_nt<false><<<gkv, 256>>>(hidden, Wv, v, S_LEN, NKV * HD, HID);

    rope_apply_kernel<<<(S_LEN * NH * 64 + 255) / 256, 256>>>(q, NH);
    rope_apply_kernel<<<(S_LEN * NKV * 64 + 255) / 256, 256>>>(k, NKV);

    size_t smem = (size_t)(2 * 64 * 129 + 64 * 64 + 64 * TOPK) * 4 + 64 * TOPK * 4;
    cudaFuncSetAttribute(attn_kernel, cudaFuncAttributeMaxDynamicSharedMemorySize,
                         (int)smem);
    attn_kernel<<<dim3(S_LEN / 64, NH), 256, smem>>>(q, k, v, at);

    sgemm_nt<false><<<gq, 256>>>(at, Wo, out, S_LEN, HID, HID);
}

// round 6
// speedup vs baseline: 1.8184x; 1.8184x over previous
#include <cuda_runtime.h>
#include <math.h>

#define S_LEN 2048
#define HID   4096
#define NH    32
#define NKV   8
#define HD    128
#define TOPK  16

// ---------------- scratch (device globals: no allocations allowed) ----------
__device__ float g_Q[(size_t)S_LEN * HID];        // 32 MB
__device__ float g_K[(size_t)S_LEN * NKV * HD];   // 8 MB
__device__ float g_V[(size_t)S_LEN * NKV * HD];   // 8 MB
__device__ float g_attn[(size_t)S_LEN * HID];     // 32 MB
__device__ float g_cos[S_LEN * 64];
__device__ float g_sin[S_LEN * 64];

// ---------------- RoPE table (host/correctly-rounded math emulation) --------
// DO NOT TOUCH: this exact pipeline is what makes the kernel pass.
__global__ void rope_table_kernel() {
    int idx = blockIdx.x * blockDim.x + threadIdx.x;
    if (idx >= S_LEN * 64) return;
    int s = idx >> 6;
    int i = idx & 63;
    double expo = (double)(2 * i) / 128.0;            // exact
    float  p    = (float)pow(500000.0, expo);         // CR powf emulation
    float  inv  = __fdiv_rn(1.0f, p);
    float  ang  = __fmul_rn((float)s, inv);
    g_cos[idx] = (float)cos((double)ang);             // CR cosf emulation
    g_sin[idx] = (float)sin((double)ang);             // CR sinf emulation
}

// ---------------- RoPE apply (in place, explicit rn mul/add, no FMA) --------
__global__ void rope_apply_kernel(float* __restrict__ X, int nheads) {
    int idx = blockIdx.x * blockDim.x + threadIdx.x;
    int total = S_LEN * nheads * 64;
    if (idx >= total) return;
    int i = idx & 63;
    int h = (idx >> 6) % nheads;
    int s = idx / (nheads * 64);
    size_t base = ((size_t)s * nheads + h) * HD + i;
    float c  = g_cos[(s << 6) + i];
    float sn = g_sin[(s << 6) + i];
    float x1 = X[base];
    float x2 = X[base + 64];
    float t1 = __fmul_rn(x1, c);
    float t2 = __fmul_rn(x2, sn);
    float u1 = __fmul_rn(x2, c);
    float u2 = __fmul_rn(x1, sn);
    X[base]      = __fadd_rn(t1, -t2);
    X[base + 64] = __fadd_rn(u1, u2);
}

// ---------------- SGEMM core: C[M,N] = A[M,K] @ B[N,K]^T -------------------
// BM=BN=128, BK=16, 256 threads, 8x8 per thread, register prefetch.
__device__ __forceinline__ void sgemm_body(
    const float* __restrict__ A, const float* __restrict__ B,
    float* __restrict__ C, int M, int N, int K, int bm, int bn)
{
    __shared__ float As[16 * 132];  // [k][m], padded
    __shared__ float Bs[16 * 132];  // [k][n], padded

    const int tid = threadIdx.x;
    const int lr = tid >> 2;            // 0..63
    const int lc = (tid & 3) << 2;      // 0,4,8,12
    const int ty = tid >> 4;            // 0..15
    const int tx = tid & 15;            // 0..15

    float acc[8][8];
#pragma unroll
    for (int i = 0; i < 8; i++)
#pragma unroll
        for (int j = 0; j < 8; j++) acc[i][j] = 0.0f;

    const float* Ap = A + (size_t)(bm + lr) * K + lc;
    const float* Bp = B + (size_t)(bn + lr) * K + lc;

    // preload tile 0
    float4 a0 = *(const float4*)(Ap);
    float4 a1 = *(const float4*)(Ap + (size_t)64 * K);
    float4 b0 = *(const float4*)(Bp);
    float4 b1 = *(const float4*)(Bp + (size_t)64 * K);

    for (int k0 = 0; k0 < K; k0 += 16) {
        __syncthreads();
        As[(lc + 0) * 132 + lr] = a0.x;
        As[(lc + 1) * 132 + lr] = a0.y;
        As[(lc + 2) * 132 + lr] = a0.z;
        As[(lc + 3) * 132 + lr] = a0.w;
        As[(lc + 0) * 132 + lr + 64] = a1.x;
        As[(lc + 1) * 132 + lr + 64] = a1.y;
        As[(lc + 2) * 132 + lr + 64] = a1.z;
        As[(lc + 3) * 132 + lr + 64] = a1.w;
        Bs[(lc + 0) * 132 + lr] = b0.x;
        Bs[(lc + 1) * 132 + lr] = b0.y;
        Bs[(lc + 2) * 132 + lr] = b0.z;
        Bs[(lc + 3) * 132 + lr] = b0.w;
        Bs[(lc + 0) * 132 + lr + 64] = b1.x;
        Bs[(lc + 1) * 132 + lr + 64] = b1.y;
        Bs[(lc + 2) * 132 + lr + 64] = b1.z;
        Bs[(lc + 3) * 132 + lr + 64] = b1.w;
        __syncthreads();

        // prefetch next tile into registers (overlaps with compute below)
        if (k0 + 16 < K) {
            a0 = *(const float4*)(Ap + k0 + 16);
            a1 = *(const float4*)(Ap + (size_t)64 * K + k0 + 16);
            b0 = *(const float4*)(Bp + k0 + 16);
            b1 = *(const float4*)(Bp + (size_t)64 * K + k0 + 16);
        }

#pragma unroll
        for (int kk = 0; kk < 16; kk++) {
            float ar[8], br[8];
            *(float4*)(ar)     = *(float4*)&As[kk * 132 + ty * 8];
            *(float4*)(ar + 4) = *(float4*)&As[kk * 132 + ty * 8 + 4];
            *(float4*)(br)     = *(float4*)&Bs[kk * 132 + tx * 8];
            *(float4*)(br + 4) = *(float4*)&Bs[kk * 132 + tx * 8 + 4];
#pragma unroll
            for (int i = 0; i < 8; i++)
#pragma unroll
                for (int j = 0; j < 8; j++)
                    acc[i][j] = fmaf(ar[i], br[j], acc[i][j]);
        }
    }

#pragma unroll
    for (int i = 0; i < 8; i++) {
        size_t row = (size_t)(bm + ty * 8 + i) * N + bn + tx * 8;
        float4 v0 = make_float4(acc[i][0], acc[i][1], acc[i][2], acc[i][3]);
        float4 v1 = make_float4(acc[i][4], acc[i][5], acc[i][6], acc[i][7]);
        *(float4*)&C[row]     = v0;
        *(float4*)&C[row + 4] = v1;
    }
}

__global__ __launch_bounds__(256) void sgemm_nt(
    const float* __restrict__ A, const float* __restrict__ B,
    float* __restrict__ C, int M, int N, int K)
{
    sgemm_body(A, B, C, M, N, K, blockIdx.y * 128, blockIdx.x * 128);
}

// K and V projections fused in one launch (blockIdx.z selects path)
__global__ __launch_bounds__(256) void sgemm_kv(
    const float* __restrict__ A,
    const float* __restrict__ Wk, const float* __restrict__ Wv,
    float* __restrict__ Ko, float* __restrict__ Vo)
{
    const float* B = blockIdx.z ? Wv : Wk;
    float*       C = blockIdx.z ? Vo : Ko;
    sgemm_body(A, B, C, S_LEN, NKV * HD, HID, blockIdx.y * 128, blockIdx.x * 128);
}

// ---------------- fused top-k attention ------------------------------------
// grid (S/64, NH), 256 threads. float4 smem operand reads (pad 132).
__global__ __launch_bounds__(256) void attn_kernel(
    const float* __restrict__ Q, const float* __restrict__ Kd,
    const float* __restrict__ V, float* __restrict__ O)
{
    extern __shared__ float sm[];
    float* Qs = sm;                      // [64][132]
    float* Ks = Qs + 64 * 132;           // [64][132]
    float* Ss = Ks + 64 * 132;           // [64][64]
    float* Tv = Ss + 64 * 64;            // [64][16] values -> weights
    int*   Ti = (int*)(Tv + 64 * TOPK);  // [64][16]

    const int tid = threadIdx.x;
    const int h   = blockIdx.y;
    const int kvh = h >> 2;
    const int q0  = blockIdx.x * 64;
    const float sqrtd = 11.313708498984761f;  // f32(sqrt(128))

    // load Q tile (64 x 128)
#pragma unroll
    for (int it = 0; it < 8; it++) {
        int idx = tid + it * 256;
        int r = idx >> 5;
        int d4 = (idx & 31) << 2;
        float4 v = *(const float4*)&Q[((size_t)(q0 + r) * NH + h) * HD + d4];
        *(float4*)&Qs[r * 132 + d4] = v;
    }
    if (tid < 64) {
#pragma unroll
        for (int j = 0; j < TOPK; j++) Tv[tid * TOPK + j] = -INFINITY;
    }
    float vmin = -INFINITY;
    int minpos = 0;

    const int ty = tid >> 4, tx = tid & 15;
    const int r0 = ty << 2, c0 = tx << 2;

    for (int kt = 0; kt < S_LEN / 64; kt++) {
        __syncthreads();
        // load K tile (64 x 128) for this kv head
#pragma unroll
        for (int it = 0; it < 8; it++) {
            int idx = tid + it * 256;
            int r = idx >> 5;
            int d4 = (idx & 31) << 2;
            float4 v = *(const float4*)&Kd[((size_t)(kt * 64 + r) * NKV + kvh) * HD + d4];
            *(float4*)&Ks[r * 132 + d4] = v;
        }
        __syncthreads();

        // 4x4 micro-tile score compute, float4 operand reads
        float acc[4][4];
#pragma unroll
        for (int i = 0; i < 4; i++)
#pragma unroll
            for (int j = 0; j < 4; j++) acc[i][j] = 0.0f;

        const float* qp = Qs + r0 * 132;
        const float* kp = Ks + c0 * 132;
#pragma unroll
        for (int d = 0; d < 128; d += 4) {
            float4 A0 = *(const float4*)(qp + d);
            float4 A1 = *(const float4*)(qp + 132 + d);
            float4 A2 = *(const float4*)(qp + 264 + d);
            float4 A3 = *(const float4*)(qp + 396 + d);
            float4 B0 = *(const float4*)(kp + d);
            float4 B1 = *(const float4*)(kp + 132 + d);
            float4 B2 = *(const float4*)(kp + 264 + d);
            float4 B3 = *(const float4*)(kp + 396 + d);
            const float4 Ax[4] = {A0, A1, A2, A3};
            const float4 Bx[4] = {B0, B1, B2, B3};
#pragma unroll
            for (int i = 0; i < 4; i++)
#pragma unroll
                for (int j = 0; j < 4; j++) {
                    float t = acc[i][j];
                    t = fmaf(Ax[i].x, Bx[j].x, t);
                    t = fmaf(Ax[i].y, Bx[j].y, t);
                    t = fmaf(Ax[i].z, Bx[j].z, t);
                    t = fmaf(Ax[i].w, Bx[j].w, t);
                    acc[i][j] = t;
                }
        }
#pragma unroll
        for (int i = 0; i < 4; i++)
#pragma unroll
            for (int j = 0; j < 4; j++)
                Ss[(r0 + i) * 64 + c0 + j] = __fdiv_rn(acc[i][j], sqrtd);
        __syncthreads();

        // per-row top-16 maintenance (threads 0..63, one per q row)
        if (tid < 64) {
            int base = kt * 64;
            float* tvp = Tv + tid * TOPK;
            int*   tip = Ti + tid * TOPK;
            const float* srow = Ss + tid * 64;
            for (int c = 0; c < 64; c++) {
                float s = srow[c];
                if (s > vmin) {
                    tvp[minpos] = s;
                    tip[minpos] = base + c;
                    vmin = tvp[0]; minpos = 0;
#pragma unroll
                    for (int j = 1; j < TOPK; j++) {
                        float t = tvp[j];
                        if (t < vmin) { vmin = t; minpos = j; }
                    }
                }
            }
        }
    }
    __syncthreads();

    // softmax over top-16 per row
    if (tid < 64) {
        float* tvp = Tv + tid * TOPK;
        float m = -INFINITY;
#pragma unroll
        for (int j = 0; j < TOPK; j++) m = fmaxf(m, tvp[j]);
        float ssum = 0.0f;
#pragma unroll
        for (int j = 0; j < TOPK; j++) {
            float e = expf(tvp[j] - m);
            tvp[j] = e;
            ssum += e;
        }
        float inv = __fdiv_rn(1.0f, ssum);
#pragma unroll
        for (int j = 0; j < TOPK; j++) tvp[j] = __fmul_rn(tvp[j], inv);
    }
    __syncthreads();

    // weighted V gather: 64 rows x 128 dims
#pragma unroll
    for (int it = 0; it < 32; it++) {
        int idx = tid + it * 256;
        int r = idx >> 7;
        int d = idx & 127;
        const float* tvp = Tv + r * TOPK;
        const int*   tip = Ti + r * TOPK;
        float acc = 0.0f;
#pragma unroll
        for (int j = 0; j < TOPK; j++) {
            float w = tvp[j];
            int ki = tip[j];
            acc = fmaf(w, V[((size_t)ki * NKV + kvh) * HD + d], acc);
        }
        O[((size_t)(q0 + r) * NH + h) * HD + d] = acc;
    }
}

// ---------------- launch ----------------------------------------------------
extern "C" void kernel_launch(void* const* d_in, const int* in_sizes, int n_in,
                              void* d_out, int out_size)
{
    const float* hidden = (const float*)d_in[0];
    const float* Wq = (const float*)d_in[1];
    const float* Wk = (const float*)d_in[2];
    const float* Wv = (const float*)d_in[3];
    const float* Wo = (const float*)d_in[4];
    float* out = (float*)d_out;

    float *q, *k, *v, *at;
    cudaGetSymbolAddress((void**)&q,  g_Q);
    cudaGetSymbolAddress((void**)&k,  g_K);
    cudaGetSymbolAddress((void**)&v,  g_V);
    cudaGetSymbolAddress((void**)&at, g_attn);

    rope_table_kernel<<<(S_LEN * 64 + 255) / 256, 256>>>();

    dim3 gq(HID / 128, S_LEN / 128);            // (32,16)
    dim3 gkv(NKV * HD / 128, S_LEN / 128, 2);   // (8,16,2) — K and V fused
    sgemm_nt<<<gq, 256>>>(hidden, Wq, q, S_LEN, HID, HID);
    sgemm_kv<<<gkv, 256>>>(hidden, Wk, Wv, k, v);

    rope_apply_kernel<<<(S_LEN * NH * 64 + 255) / 256, 256>>>(q, NH);
    rope_apply_kernel<<<(S_LEN * NKV * 64 + 255) / 256, 256>>>(k, NKV);

    size_t smem = (size_t)(2 * 64 * 132 + 64 * 64 + 64 * TOPK) * 4 + 64 * TOPK * 4;
    cudaFuncSetAttribute(attn_kernel, cudaFuncAttributeMaxDynamicSharedMemorySize,
                         (int)smem);
    attn_kernel<<<dim3(S_LEN / 64, NH), 256, smem>>>(q, k, v, at);

    sgemm_nt<<<gq, 256>>>(at, Wo, out, S_LEN, HID, HID);
}